// round 12
// baseline (speedup 1.0000x reference)
#include <cuda_runtime.h>

#define FULLMASK 0xffffffffu

static __device__ __forceinline__ float fixv(float p) {
    return (p == -1.0f) ? 0.0f : p;
}

static __device__ __forceinline__ float tanh_fast(float x) {
    float y;
    asm("tanh.approx.f32 %0, %1;" : "=f"(y) : "f"(x));
    return y;
}

// One CTA per batch image, 256 threads, 2 cols x 8 rows per thread.
// Warp w (of 8) owns image rows 8w..8w+7; lane j owns cols 2j,2j+1.
//
// Separable stencil, register-resident band: per iteration each thread
// builds horizontal 3-sums h0..h7 for its 8 rows (16 shuffles), stores only
// the two BOUNDARY rows (h0, h7) to smem, computes the 6 INTERIOR outputs
// before the barrier (75% of the tanh work hides the barrier + LDS latency),
// then loads the 2 halo h-rows and finishes the boundary outputs.
__global__ __launch_bounds__(256, 1)
void prop_kernel(const float* __restrict__ X,
                 const float* __restrict__ pred,
                 const float* __restrict__ w,
                 const float* __restrict__ a,
                 const float* __restrict__ bias,
                 const float* __restrict__ scalar,
                 float* __restrict__ out)
{
    constexpr int NS = 64;          // image side
    constexpr int HH = NS * NS;     // 4096 pixels
    constexpr int SROWS = 66;       // +1 zero halo row each side (idx = row+1)
    constexpr int ITERS = 12;

    __shared__ float Hs[2][SROWS * NS];   // boundary h-rows, double buffered

    const int b    = blockIdx.x;
    const int t    = threadIdx.x;
    const int wrp  = t >> 5;        // 0..7 -> rows 8w..8w+7
    const int lane = t & 31;        // cols 2j, 2j+1

    // Zero halo rows (halo idx 0 and 65) in both buffers, once.
    if (t < NS) {
        Hs[0][t] = 0.f;            Hs[1][t] = 0.f;
        Hs[0][65 * NS + t] = 0.f;  Hs[1][65 * NS + t] = 0.f;
    }

    const float s  = scalar[0];
    const int r0 = wrp * 8;             // first owned row
    const int c  = lane * 2;            // left col
    const int g0 = b * HH + r0 * NS + c;
    const int p0 = r0 * NS + c;

    // ---- per-row params: cs = s*(u_fix+bias+a*X), sw = s*w ----
    float2 u0, u1, u2, u3, u4, u5, u6, u7;
    float2 cs0, cs1, cs2, cs3, cs4, cs5, cs6, cs7;
    float2 sw0, sw1, sw2, sw3, sw4, sw5, sw6, sw7;
    {
        float2 pr, xx, ww, aa, bb;
        #define SETUP(K)                                                     \
            pr = *(const float2*)(pred + g0 + (K) * NS);                     \
            xx = *(const float2*)(X    + g0 + (K) * NS);                     \
            ww = *(const float2*)(w    + p0 + (K) * NS);                     \
            aa = *(const float2*)(a    + p0 + (K) * NS);                     \
            bb = *(const float2*)(bias + p0 + (K) * NS);                     \
            cs##K.x = s * (fixv(pr.x) + bb.x + aa.x * xx.x);                 \
            cs##K.y = s * (fixv(pr.y) + bb.y + aa.y * xx.y);                 \
            sw##K.x = s * ww.x;  sw##K.y = s * ww.y;                         \
            u##K = pr;
        SETUP(0) SETUP(1) SETUP(2) SETUP(3)
        SETUP(4) SETUP(5) SETUP(6) SETUP(7)
        #undef SETUP
    }

    // smem indices (image row r -> halo idx r+1)
    const int stT = (r0 + 1) * NS + c;   // own top boundary h-row (row 8w)
    const int stB = (r0 + 8) * NS + c;   // own bottom boundary h-row (row 8w+7)
    const int ldU =  r0      * NS + c;   // halo above (row 8w-1)
    const int ldD = (r0 + 9) * NS + c;   // halo below (row 8w+8)

    __syncthreads();

    #pragma unroll
    for (int it = 0; it < ITERS; ++it) {
        float* __restrict__ Hc = Hs[it & 1];

        // ---- horizontal 3-sums for all 8 owned rows (16 shuffles) ----
        float2 h0, h1, h2, h3, h4, h5, h6, h7;
        {
            float sp, lf, rt;
            #define HSUM(K)                                                  \
                sp = u##K.x + u##K.y;                                        \
                lf = __shfl_up_sync  (FULLMASK, u##K.y, 1);                  \
                rt = __shfl_down_sync(FULLMASK, u##K.x, 1);                  \
                if (lane == 0)  lf = 0.f;                                    \
                if (lane == 31) rt = 0.f;                                    \
                h##K = make_float2(lf + sp, sp + rt);
            HSUM(0) HSUM(1) HSUM(2) HSUM(3)
            HSUM(4) HSUM(5) HSUM(6) HSUM(7)
            #undef HSUM
        }

        // ---- publish boundary rows only ----
        *(float2*)&Hc[stT] = h0;
        *(float2*)&Hc[stB] = h7;

        // ---- 6 interior outputs: no smem dependency, BEFORE the barrier ----
        #define INTR(K, A, B, C)                                             \
            u##K.x = tanh_fast(fmaf(sw##K.x, h##A.x + h##B.x + h##C.x, cs##K.x)); \
            u##K.y = tanh_fast(fmaf(sw##K.y, h##A.y + h##B.y + h##C.y, cs##K.y));
        INTR(1, 0, 1, 2)
        INTR(2, 1, 2, 3)
        INTR(3, 2, 3, 4)
        INTR(4, 3, 4, 5)
        INTR(5, 4, 5, 6)
        INTR(6, 5, 6, 7)
        #undef INTR

        // partial boundary sums (register part)
        float2 t0 = make_float2(h0.x + h1.x, h0.y + h1.y);
        float2 t7 = make_float2(h6.x + h7.x, h6.y + h7.y);

        __syncthreads();

        // ---- halo h-rows, finish boundary outputs ----
        const float2 hU = *(const float2*)&Hc[ldU];
        const float2 hD = *(const float2*)&Hc[ldD];

        u0.x = tanh_fast(fmaf(sw0.x, hU.x + t0.x, cs0.x));
        u0.y = tanh_fast(fmaf(sw0.y, hU.y + t0.y, cs0.y));
        u7.x = tanh_fast(fmaf(sw7.x, t7.x + hD.x, cs7.x));
        u7.y = tanh_fast(fmaf(sw7.y, t7.y + hD.y, cs7.y));
    }

    *(float2*)(out + g0)          = u0;
    *(float2*)(out + g0 + NS)     = u1;
    *(float2*)(out + g0 + 2 * NS) = u2;
    *(float2*)(out + g0 + 3 * NS) = u3;
    *(float2*)(out + g0 + 4 * NS) = u4;
    *(float2*)(out + g0 + 5 * NS) = u5;
    *(float2*)(out + g0 + 6 * NS) = u6;
    *(float2*)(out + g0 + 7 * NS) = u7;
}

extern "C" void kernel_launch(void* const* d_in, const int* in_sizes, int n_in,
                              void* d_out, int out_size) {
    const float* X      = (const float*)d_in[0];
    const float* pred   = (const float*)d_in[1];
    const float* w      = (const float*)d_in[2];
    const float* a      = (const float*)d_in[3];
    const float* bias   = (const float*)d_in[4];
    const float* scalar = (const float*)d_in[5];
    float* out = (float*)d_out;

    const int B = in_sizes[0] / 4096;   // batch = 128
    prop_kernel<<<B, 256>>>(X, pred, w, a, bias, scalar, out);
}

// round 13
// speedup vs baseline: 1.0295x; 1.0295x over previous
#include <cuda_runtime.h>

#define FULLMASK 0xffffffffu

static __device__ __forceinline__ float fixv(float p) {
    return (p == -1.0f) ? 0.0f : p;
}

static __device__ __forceinline__ float tanh_fast(float x) {
    float y;
    asm("tanh.approx.f32 %0, %1;" : "=f"(y) : "f"(x));
    return y;
}

// TWO CTAs per batch image, 352 threads each, 2 cols x 4 rows per thread.
// CTA (img, half): half 0 covers image rows 0..43 and OUTPUTS rows 0..31;
// half 1 covers rows 20..63 and outputs rows 32..63. The cut edge is treated
// as a zero halo (same as the true image edge); the resulting error advances
// one row per iteration and after 12 iterations has not reached the output
// half, so outputs are exactly the single-CTA results.
//
// Why: grid 256 puts ~2 independent CTAs on each SM. Each CTA is its own
// barrier domain, so while one CTA's warps wait at __syncthreads, the other
// CTA's warps issue — fixing the ~40% issue efficiency that capped all
// single-CTA variants, at the price of +37% redundant row work.
//
// Within a CTA: R10 structure. Warp b (of 11) owns local rows 4b..4b+3;
// boundary h-rows via smem, interior h-rows register-resident, interior tanh
// computed before the barrier.
__global__ __launch_bounds__(352, 1)
void prop_kernel(const float* __restrict__ X,
                 const float* __restrict__ pred,
                 const float* __restrict__ w,
                 const float* __restrict__ a,
                 const float* __restrict__ bias,
                 const float* __restrict__ scalar,
                 float* __restrict__ out)
{
    constexpr int NS = 64;          // image side
    constexpr int HH = NS * NS;     // 4096 pixels
    constexpr int LROWS = 44;       // local window rows
    constexpr int SROWS = LROWS + 2;// + zero halo row each side (idx = lr+1)
    constexpr int ITERS = 12;

    __shared__ float Hs[2][SROWS * NS];   // boundary h-rows, double buffered

    const int bx   = blockIdx.x;
    const int img  = bx >> 1;
    const int half = bx & 1;
    const int rowOff = half ? (NS - LROWS) : 0;   // 20 or 0

    const int t    = threadIdx.x;
    const int wrp  = t >> 5;        // 0..10 -> local rows 4b..4b+3
    const int lane = t & 31;        // cols 2j, 2j+1

    // Zero halo rows (halo idx 0 and LROWS+1) in both buffers, once.
    if (t < NS) {
        Hs[0][t] = 0.f;                     Hs[1][t] = 0.f;
        Hs[0][(LROWS + 1) * NS + t] = 0.f;  Hs[1][(LROWS + 1) * NS + t] = 0.f;
    }

    const float s  = scalar[0];
    const int lr0 = wrp * 4;                    // first owned local row
    const int r0  = rowOff + lr0;               // first owned image row
    const int c   = lane * 2;                   // left col
    const int g0  = img * HH + r0 * NS + c;
    const int p0  = r0 * NS + c;

    // ---- per-row params: cs = s*(u_fix+bias+a*X), sw = s*w ----
    float2 u0, u1, u2, u3;
    float2 cs0, cs1, cs2, cs3, sw0, sw1, sw2, sw3;
    {
        float2 pr, xx, ww, aa, bb;
        #define SETUP(K)                                                     \
            pr = *(const float2*)(pred + g0 + (K) * NS);                     \
            xx = *(const float2*)(X    + g0 + (K) * NS);                     \
            ww = *(const float2*)(w    + p0 + (K) * NS);                     \
            aa = *(const float2*)(a    + p0 + (K) * NS);                     \
            bb = *(const float2*)(bias + p0 + (K) * NS);                     \
            cs##K.x = s * (fixv(pr.x) + bb.x + aa.x * xx.x);                 \
            cs##K.y = s * (fixv(pr.y) + bb.y + aa.y * xx.y);                 \
            sw##K.x = s * ww.x;  sw##K.y = s * ww.y;                         \
            u##K = pr;
        SETUP(0) SETUP(1) SETUP(2) SETUP(3)
        #undef SETUP
    }

    // smem indices (local row lr -> halo idx lr+1)
    const int stT = (lr0 + 1) * NS + c;   // own top boundary h-row
    const int stB = (lr0 + 4) * NS + c;   // own bottom boundary h-row
    const int ldU =  lr0      * NS + c;   // halo above
    const int ldD = (lr0 + 5) * NS + c;   // halo below

    __syncthreads();

    #pragma unroll
    for (int it = 0; it < ITERS; ++it) {
        float* __restrict__ Hc = Hs[it & 1];

        // ---- horizontal 3-sums for all 4 owned rows (8 shuffles) ----
        float2 h0, h1, h2, h3;
        {
            float s0 = u0.x + u0.y, s1 = u1.x + u1.y;
            float s2 = u2.x + u2.y, s3 = u3.x + u3.y;
            float l0 = __shfl_up_sync  (FULLMASK, u0.y, 1);
            float r0s= __shfl_down_sync(FULLMASK, u0.x, 1);
            float l1 = __shfl_up_sync  (FULLMASK, u1.y, 1);
            float r1s= __shfl_down_sync(FULLMASK, u1.x, 1);
            float l2 = __shfl_up_sync  (FULLMASK, u2.y, 1);
            float r2s= __shfl_down_sync(FULLMASK, u2.x, 1);
            float l3 = __shfl_up_sync  (FULLMASK, u3.y, 1);
            float r3s= __shfl_down_sync(FULLMASK, u3.x, 1);
            if (lane == 0)  { l0 = 0.f; l1 = 0.f; l2 = 0.f; l3 = 0.f; }
            if (lane == 31) { r0s = 0.f; r1s = 0.f; r2s = 0.f; r3s = 0.f; }
            h0 = make_float2(l0 + s0, s0 + r0s);
            h1 = make_float2(l1 + s1, s1 + r1s);
            h2 = make_float2(l2 + s2, s2 + r2s);
            h3 = make_float2(l3 + s3, s3 + r3s);
        }

        // ---- publish boundary rows only ----
        *(float2*)&Hc[stT] = h0;
        *(float2*)&Hc[stB] = h3;

        // ---- interior outputs: no smem dependency, BEFORE the barrier ----
        float2 v1 = make_float2(h0.x + h1.x + h2.x, h0.y + h1.y + h2.y);
        float2 v2 = make_float2(h1.x + h2.x + h3.x, h1.y + h2.y + h3.y);
        u1.x = tanh_fast(fmaf(sw1.x, v1.x, cs1.x));
        u1.y = tanh_fast(fmaf(sw1.y, v1.y, cs1.y));
        u2.x = tanh_fast(fmaf(sw2.x, v2.x, cs2.x));
        u2.y = tanh_fast(fmaf(sw2.y, v2.y, cs2.y));

        // partial boundary sums (register part)
        float2 t0 = make_float2(h0.x + h1.x, h0.y + h1.y);
        float2 t3 = make_float2(h2.x + h3.x, h2.y + h3.y);

        __syncthreads();

        // ---- halo h-rows, finish boundary outputs ----
        const float2 hU = *(const float2*)&Hc[ldU];
        const float2 hD = *(const float2*)&Hc[ldD];

        u0.x = tanh_fast(fmaf(sw0.x, hU.x + t0.x, cs0.x));
        u0.y = tanh_fast(fmaf(sw0.y, hU.y + t0.y, cs0.y));
        u3.x = tanh_fast(fmaf(sw3.x, t3.x + hD.x, cs3.x));
        u3.y = tanh_fast(fmaf(sw3.y, t3.y + hD.y, cs3.y));
    }

    // Write only the clean half: half 0 -> image rows 0..31 (warps 0..7),
    // half 1 -> image rows 32..63 (local rows >= 12, warps 3..10).
    const bool writer = half ? (wrp >= 3) : (wrp < 8);
    if (writer) {
        *(float2*)(out + g0)          = u0;
        *(float2*)(out + g0 + NS)     = u1;
        *(float2*)(out + g0 + 2 * NS) = u2;
        *(float2*)(out + g0 + 3 * NS) = u3;
    }
}

extern "C" void kernel_launch(void* const* d_in, const int* in_sizes, int n_in,
                              void* d_out, int out_size) {
    const float* X      = (const float*)d_in[0];
    const float* pred   = (const float*)d_in[1];
    const float* w      = (const float*)d_in[2];
    const float* a      = (const float*)d_in[3];
    const float* bias   = (const float*)d_in[4];
    const float* scalar = (const float*)d_in[5];
    float* out = (float*)d_out;

    const int B = in_sizes[0] / 4096;   // batch = 128
    prop_kernel<<<2 * B, 352>>>(X, pred, w, a, bias, scalar, out);
}